// round 16
// baseline (speedup 1.0000x reference)
#include <cuda_runtime.h>
#include <cstdint>

#define BT 32
#define H 128
#define W 128
#define C 64
#define NPIX (H*W)          // 16384
#define M 256

// ---------------- device scratch (no allocs allowed) ----------------
__device__ float g_sum[BT*M*C];          // 2 MB
__device__ float g_sq [BT*M*C];          // 2 MB
__device__ float g_cnt[BT*M];            // 32 KB
__device__ unsigned char g_edges[BT*NPIX]; // 512 KB, 4 fwd-dir bits per pixel
__device__ unsigned char g_seg  [BT*NPIX]; // 512 KB, segment id 0..255

// ---------------- K0: zero accumulators ----------------
__global__ void k_zero() {
    int tid = blockIdx.x * blockDim.x + threadIdx.x;
    if (tid < BT*M*C) { g_sum[tid] = 0.f; g_sq[tid] = 0.f; }
    if (tid < BT*M)   g_cnt[tid] = 0.f;
}

// ---------------- K1: forward-direction edge bits ----------------
// Tile: 16x16 output pixels. smem cells: rows 0..16 (17), cols -1..16 (18) = 306 cells.
// Layout sm[v][cell], v = float4 channel group (16), stride 307 f4 (pad) so the
// compute-phase reads (consecutive cells across lanes) are conflict-free.
#define K1_CELLS 306
#define K1_CSTR  307
#define K1_SMEM  (16 * K1_CSTR * 16)     // 78,592 bytes

__global__ void __launch_bounds__(256) k_edges(const float4* __restrict__ feat) {
    extern __shared__ float4 sm[];
    int tx = threadIdx.x & 15, ty = threadIdx.x >> 4;
    int gy0 = blockIdx.y * 16, gx0 = blockIdx.x * 16;
    int img = blockIdx.z;
    const float4* fimg = feat + (size_t)img * (NPIX * 16);

    // cooperative load: consecutive lanes -> consecutive v (contiguous gmem)
    for (int idx = threadIdx.x; idx < K1_CELLS * 16; idx += 256) {
        int cell = idx >> 4, v = idx & 15;
        int r = cell / 18;
        int cc = cell - r * 18;              // 0..17 -> gx = gx0 + cc - 1
        int gy = gy0 + r, gx = gx0 + cc - 1;
        float4 val;
        if (gy < H && gx >= 0 && gx < W)
            val = fimg[(gy * W + gx) * 16 + v];
        else
            val = make_float4(1e6f, 1e6f, 1e6f, 1e6f); // matches reference OOB fill
        sm[v * K1_CSTR + cell] = val;
    }
    __syncthreads();

    int cellC = ty * 18 + tx + 1;
    float s0 = 0.f, s1 = 0.f, s2 = 0.f, s3 = 0.f;
    #pragma unroll
    for (int v = 0; v < 16; v++) {
        const float4* row = sm + v * K1_CSTR + cellC;
        float4 fc = row[0];
        float4 aE  = row[1];      // (0,+1)
        float4 aSW = row[17];     // (+1,-1)
        float4 aS  = row[18];     // (+1, 0)
        float4 aSE = row[19];     // (+1,+1)
        float t;
        t = fc.x - aE.x;  s0 += t*t;  t = fc.y - aE.y;  s0 += t*t;
        t = fc.z - aE.z;  s0 += t*t;  t = fc.w - aE.w;  s0 += t*t;
        t = fc.x - aSW.x; s1 += t*t;  t = fc.y - aSW.y; s1 += t*t;
        t = fc.z - aSW.z; s1 += t*t;  t = fc.w - aSW.w; s1 += t*t;
        t = fc.x - aS.x;  s2 += t*t;  t = fc.y - aS.y;  s2 += t*t;
        t = fc.z - aS.z;  s2 += t*t;  t = fc.w - aS.w;  s2 += t*t;
        t = fc.x - aSE.x; s3 += t*t;  t = fc.y - aSE.y; s3 += t*t;
        t = fc.z - aSE.z; s3 += t*t;  t = fc.w - aSE.w; s3 += t*t;
    }
    // edge iff affinity>0.5 iff dist<1 iff sum_sq < 1 (1e-12 epsilon is negligible)
    unsigned e = (unsigned)(s0 < 1.0f)
               | ((unsigned)(s1 < 1.0f) << 1)
               | ((unsigned)(s2 < 1.0f) << 2)
               | ((unsigned)(s3 < 1.0f) << 3);
    g_edges[img * NPIX + (gy0 + ty) * W + (gx0 + tx)] = (unsigned char)e;
}

// ---------------- K2: label propagation (Jacobi, <=40 iters, fixed-point early
// exit) fused with contiguous relabel (rank of present labels, capped at 255) --
#define SM_LABA  0
#define SM_LABB  32768
#define SM_EG    65536
#define SM_BITS  81920
#define SM_WPFX  83968
#define SM_WSUM  86016
#define SM_FLAGS 86080
#define K2_SMEM  (86080 + 40*4)          // 86,240 bytes

__global__ void __launch_bounds__(1024, 1) k_prop() {
    extern __shared__ char smraw[];
    unsigned short* labA = (unsigned short*)(smraw + SM_LABA);
    unsigned short* labB = (unsigned short*)(smraw + SM_LABB);
    unsigned char*  eg   = (unsigned char*) (smraw + SM_EG);
    unsigned int*   bits = (unsigned int*)  (smraw + SM_BITS);
    int* wpfx  = (int*)(smraw + SM_WPFX);
    int* wsum  = (int*)(smraw + SM_WSUM);
    int* flags = (int*)(smraw + SM_FLAGS);

    int tid = threadIdx.x;
    int img = blockIdx.x;

    ((uint4*)eg)[tid] = ((const uint4*)(g_edges + img * NPIX))[tid];
    #pragma unroll
    for (int i = 0; i < 16; i++) labA[tid + i * 1024] = (unsigned short)(tid + i * 1024);
    if (tid < 40) flags[tid] = 0;
    __syncthreads();

    unsigned short* cur = labA;
    unsigned short* nxt = labB;
    for (int it = 0; it < 40; ++it) {
        int changed = 0;
        #pragma unroll
        for (int i = 0; i < 16; i++) {
            int p = tid + i * 1024;
            int old = cur[p];
            int m = old;
            unsigned e = eg[p];
            // forward edges: bits guarantee neighbor is in-image
            if (e & 1u) { int t = cur[p + 1];   if (t < m) m = t; }
            if (e & 2u) { int t = cur[p + 127]; if (t < m) m = t; }
            if (e & 4u) { int t = cur[p + 128]; if (t < m) m = t; }
            if (e & 8u) { int t = cur[p + 129]; if (t < m) m = t; }
            // backward edges come from the neighbor's forward bit
            int x = p & 127;
            if (x > 0 && (eg[p - 1] & 1u))   { int t = cur[p - 1];   if (t < m) m = t; }
            if (p >= 128) {
                if (x < 127 && (eg[p - 127] & 2u)) { int t = cur[p - 127]; if (t < m) m = t; }
                if (eg[p - 128] & 4u)              { int t = cur[p - 128]; if (t < m) m = t; }
                if (x > 0 && (eg[p - 129] & 8u))   { int t = cur[p - 129]; if (t < m) m = t; }
            }
            nxt[p] = (unsigned short)m;
            changed |= (m != old);
        }
        if (changed) flags[it] = 1;
        __syncthreads();
        unsigned short* t = cur; cur = nxt; nxt = t;
        if (!flags[it]) break;   // fixed point: all remaining iterations identity
    }

    // ---- relabel: presence bitmap + popcount prefix scan ----
    if (tid < 512) bits[tid] = 0u;
    __syncthreads();
    #pragma unroll
    for (int i = 0; i < 16; i++) {
        int lab = cur[tid + i * 1024];
        atomicOr(&bits[lab >> 5], 1u << (lab & 31));
    }
    __syncthreads();
    if (tid < 512) {
        int lane = tid & 31;
        int pc = __popc(bits[tid]);
        int v = pc;
        #pragma unroll
        for (int o = 1; o < 32; o <<= 1) {
            int t = __shfl_up_sync(0xFFFFFFFFu, v, o);
            if (lane >= o) v += t;
        }
        wpfx[tid] = v - pc;                  // exclusive within warp
        if (lane == 31) wsum[tid >> 5] = v;  // warp total
    }
    __syncthreads();
    if (tid < 16) {
        int orig = wsum[tid];
        int v = orig;
        #pragma unroll
        for (int o = 1; o < 16; o <<= 1) {
            int t = __shfl_up_sync(0x0000FFFFu, v, o);
            if (tid >= o) v += t;
        }
        wsum[tid] = v - orig;                // exclusive warp base
    }
    __syncthreads();
    #pragma unroll
    for (int i = 0; i < 16; i++) {
        int p = tid + i * 1024;
        int lab = cur[p];
        int w = lab >> 5;
        unsigned mask = (2u << (lab & 31)) - 1u;  // inclusive mask (2<<31 wraps to 0 -> all ones)
        int rank = wpfx[w] + wsum[w >> 5] + __popc(bits[w] & mask) - 1;
        g_seg[img * NPIX + p] = (unsigned char)(rank < 255 ? rank : 255);
    }
}

// ---------------- K4: per-segment sum / sumsq / count ----------------
// Thread = (channel c, pixel stripe). Warp lanes = 32 consecutive channels of the
// SAME pixel -> 128B coalesced feature loads, broadcast seg load. Register
// run-length accumulation; atomics only on segment change.
__global__ void __launch_bounds__(512) k_agg(const float* __restrict__ feat) {
    int img = blockIdx.y;
    int c = threadIdx.x & 63;
    int stripe = (threadIdx.x >> 6) + (blockIdx.x << 3);  // 0..127
    int p0 = stripe << 7;                                  // 128 pixels each
    const unsigned char* segp = g_seg + img * NPIX;
    const float* fp = feat + (size_t)img * NPIX * C + c;

    int cur = segp[p0];
    float asum = 0.f, asq = 0.f, runlen = 0.f;
    for (int i = 0; i < 128; i++) {
        int p = p0 + i;
        int s = segp[p];
        float f = __ldg(&fp[(size_t)p * C]);
        if (s != cur) {
            int base = (img * M + cur) * C + c;
            atomicAdd(&g_sum[base], asum);
            atomicAdd(&g_sq[base], asq);
            if (c == 0) atomicAdd(&g_cnt[img * M + cur], runlen);
            cur = s; asum = 0.f; asq = 0.f; runlen = 0.f;
        }
        asum += f;
        asq  += f * f;
        runlen += 1.f;
    }
    int base = (img * M + cur) * C + c;
    atomicAdd(&g_sum[base], asum);
    atomicAdd(&g_sq[base], asq);
    if (c == 0) atomicAdd(&g_cnt[img * M + cur], runlen);
}

// ---------------- K5: finalize mean/var ----------------
__global__ void k_fin(float* __restrict__ out) {
    int tid = blockIdx.x * blockDim.x + threadIdx.x;
    if (tid >= BT*M*C) return;
    int c = tid & (C - 1);
    int seg = tid >> 6;                       // bt*M + m
    float d = fmaxf(g_cnt[seg], 1.0f);
    float mean = g_sum[tid] / d;
    float var = fmaxf(g_sq[tid] / d - mean * mean, 0.0f);
    size_t ob = (size_t)seg * (2 * C) + c;
    out[ob]     = mean;
    out[ob + C] = var;
}

// ---------------- launch ----------------
extern "C" void kernel_launch(void* const* d_in, const int* in_sizes, int n_in,
                              void* d_out, int out_size) {
    (void)in_sizes; (void)n_in; (void)out_size;
    const float* feat = (const float*)d_in[0];
    float* out = (float*)d_out;

    cudaFuncSetAttribute(k_edges, cudaFuncAttributeMaxDynamicSharedMemorySize, K1_SMEM);
    cudaFuncSetAttribute(k_prop,  cudaFuncAttributeMaxDynamicSharedMemorySize, K2_SMEM);

    k_zero<<<2048, 256>>>();
    k_edges<<<dim3(8, 8, BT), 256, K1_SMEM>>>((const float4*)feat);
    k_prop<<<BT, 1024, K2_SMEM>>>();
    k_agg<<<dim3(16, BT), 512>>>(feat);
    k_fin<<<2048, 256>>>(out);
}

// round 17
// speedup vs baseline: 1.0308x; 1.0308x over previous
#include <cuda_runtime.h>
#include <cstdint>

#define BT 32
#define H 128
#define W 128
#define C 64
#define NPIX (H*W)          // 16384
#define M 256

// ---------------- device scratch (no allocs allowed) ----------------
__device__ float g_sum[BT*M*C];            // 2 MB
__device__ float g_sq [BT*M*C];            // 2 MB
__device__ float g_cnt[BT*M];              // 32 KB
__device__ unsigned char g_edges[BT*NPIX]; // 512 KB, 4 fwd-dir bits per pixel
__device__ unsigned char g_seg  [BT*NPIX]; // 512 KB, segment id 0..255

// ================= K1: forward-direction edge bits ==================
// 32x32 output tile. Halo cells: rows 0..32 (33), cols -1..32 (34) = 1122.
// Channel-streamed: 16 float4 chunks through a double-buffered smem stage
// filled with cp.async; each thread computes a 1x4 pixel strip (11 f4 reads
// per chunk for 16 pixel-dir accumulators).
#define CELLS   1122
#define K1_SMEM (2*CELLS*16)   // 35904 B

__device__ __forceinline__ void cp16(uint32_t saddr, const void* g) {
    asm volatile("cp.async.cg.shared.global [%0], [%1], 16;" :: "r"(saddr), "l"(g));
}
__device__ __forceinline__ void cp_commit() {
    asm volatile("cp.async.commit_group;");
}
__device__ __forceinline__ void cp_wait1() {
    asm volatile("cp.async.wait_group 1;");
}
__device__ __forceinline__ void cp_wait0() {
    asm volatile("cp.async.wait_group 0;");
}
__device__ __forceinline__ void acc4(float& s, float4 u, float4 w) {
    float t;
    t = u.x - w.x; s = fmaf(t, t, s);
    t = u.y - w.y; s = fmaf(t, t, s);
    t = u.z - w.z; s = fmaf(t, t, s);
    t = u.w - w.w; s = fmaf(t, t, s);
}

__global__ void __launch_bounds__(256) k_edges(const float4* __restrict__ feat) {
    extern __shared__ float4 sm[];
    int tid = threadIdx.x;
    int sx = tid & 7;          // strip column (4 pixels each)
    int ty = tid >> 3;         // 0..31
    int gy0 = blockIdx.y * 32, gx0 = blockIdx.x * 32;
    int img = blockIdx.z;
    const float4* fimg = feat + (size_t)img * (NPIX * 16);

    // ---- fold-in: zero accumulators (consumed only by k_agg, later) ----
    {
        int b = (blockIdx.z * 16) + blockIdx.y * 4 + blockIdx.x;   // 0..511
        float4 z = make_float4(0.f, 0.f, 0.f, 0.f);
        ((float4*)g_sum)[b * 256 + tid] = z;
        ((float4*)g_sq )[b * 256 + tid] = z;
        if (tid < 4) ((float4*)g_cnt)[b * 4 + tid] = z;
    }

    uint32_t sbase = (uint32_t)__cvta_generic_to_shared(sm);
    const float4 fill = make_float4(1e6f, 1e6f, 1e6f, 1e6f);

    // chunk loader: 1122 cells, 5 strided passes of 256 threads
    auto loadChunk = [&](int v, int bi) {
        uint32_t sb = sbase + (uint32_t)(bi * CELLS * 16);
        float4* sg = sm + bi * CELLS;
        #pragma unroll
        for (int k = 0; k < 5; k++) {
            int cell = tid + k * 256;
            if (cell < CELLS) {
                int r = cell / 34;
                int cc = cell - r * 34;
                int gy = gy0 + r, gx = gx0 + cc - 1;
                if (gy < H && gx >= 0 && gx < W)
                    cp16(sb + cell * 16, fimg + (gy * W + gx) * 16 + v);
                else
                    sg[cell] = fill;
            }
        }
    };

    float accE0=0,accE1=0,accE2=0,accE3=0;
    float accSW0=0,accSW1=0,accSW2=0,accSW3=0;
    float accS0=0,accS1=0,accS2=0,accS3=0;
    float accSE0=0,accSE1=0,accSE2=0,accSE3=0;

    int baseA = ty * 34 + sx * 4 + 1;   // row ty, cols x..x+4
    int baseB = baseA + 33;             // row ty+1, cols x-1..x+4

    loadChunk(0, 0);
    cp_commit();

    #pragma unroll 1
    for (int v = 0; v < 16; v++) {
        if (v < 15) { loadChunk(v + 1, (v + 1) & 1); }
        cp_commit();
        cp_wait1();
        __syncthreads();                // chunk v visible to all

        const float4* bb = sm + (v & 1) * CELLS;
        float4 A0 = bb[baseA + 0], A1 = bb[baseA + 1], A2 = bb[baseA + 2],
               A3 = bb[baseA + 3], A4 = bb[baseA + 4];
        float4 B0 = bb[baseB + 0], B1 = bb[baseB + 1], B2 = bb[baseB + 2],
               B3 = bb[baseB + 3], B4 = bb[baseB + 4], B5 = bb[baseB + 5];

        acc4(accE0,  A0, A1); acc4(accSW0, A0, B0); acc4(accS0, A0, B1); acc4(accSE0, A0, B2);
        acc4(accE1,  A1, A2); acc4(accSW1, A1, B1); acc4(accS1, A1, B2); acc4(accSE1, A1, B3);
        acc4(accE2,  A2, A3); acc4(accSW2, A2, B2); acc4(accS2, A2, B3); acc4(accSE2, A2, B4);
        acc4(accE3,  A3, A4); acc4(accSW3, A3, B3); acc4(accS3, A3, B4); acc4(accSE3, A3, B5);

        __syncthreads();                // done reading buf[v&1] before reuse
    }
    cp_wait0();

    // edge iff affinity > 0.5 iff dist < 1 iff sum_sq < 1
    uchar4 e4;
    e4.x = (unsigned char)((accE0<1.f) | ((accSW0<1.f)<<1) | ((accS0<1.f)<<2) | ((accSE0<1.f)<<3));
    e4.y = (unsigned char)((accE1<1.f) | ((accSW1<1.f)<<1) | ((accS1<1.f)<<2) | ((accSE1<1.f)<<3));
    e4.z = (unsigned char)((accE2<1.f) | ((accSW2<1.f)<<1) | ((accS2<1.f)<<2) | ((accSE2<1.f)<<3));
    e4.w = (unsigned char)((accE3<1.f) | ((accSW3<1.f)<<1) | ((accS3<1.f)<<2) | ((accSE3<1.f)<<3));
    *(uchar4*)&g_edges[img * NPIX + (gy0 + ty) * W + gx0 + sx * 4] = e4;
}

// ====== K2: label propagation (Jacobi, <=40 iters, fixed-point early exit)
//        fused with contiguous relabel (rank of present labels, capped) ======
#define SM_LABA  0
#define SM_LABB  32768
#define SM_EG    65536
#define SM_BITS  81920
#define SM_WPFX  83968
#define SM_WSUM  86016
#define SM_FLAGS 86080
#define K2_SMEM  (86080 + 40*4)

__global__ void __launch_bounds__(1024, 1) k_prop() {
    extern __shared__ char smraw[];
    unsigned short* labA = (unsigned short*)(smraw + SM_LABA);
    unsigned short* labB = (unsigned short*)(smraw + SM_LABB);
    unsigned char*  eg   = (unsigned char*) (smraw + SM_EG);
    unsigned int*   bits = (unsigned int*)  (smraw + SM_BITS);
    int* wpfx  = (int*)(smraw + SM_WPFX);
    int* wsum  = (int*)(smraw + SM_WSUM);
    int* flags = (int*)(smraw + SM_FLAGS);

    int tid = threadIdx.x;
    int img = blockIdx.x;

    ((uint4*)eg)[tid] = ((const uint4*)(g_edges + img * NPIX))[tid];
    #pragma unroll
    for (int i = 0; i < 16; i++) labA[tid + i * 1024] = (unsigned short)(tid + i * 1024);
    if (tid < 40) flags[tid] = 0;
    __syncthreads();

    unsigned short* cur = labA;
    unsigned short* nxt = labB;
    for (int it = 0; it < 40; ++it) {
        int changed = 0;
        #pragma unroll
        for (int i = 0; i < 16; i++) {
            int p = tid + i * 1024;
            int old = cur[p];
            int m = old;
            unsigned e = eg[p];
            if (e & 1u) { int t = cur[p + 1];   if (t < m) m = t; }
            if (e & 2u) { int t = cur[p + 127]; if (t < m) m = t; }
            if (e & 4u) { int t = cur[p + 128]; if (t < m) m = t; }
            if (e & 8u) { int t = cur[p + 129]; if (t < m) m = t; }
            int x = p & 127;
            if (x > 0 && (eg[p - 1] & 1u))   { int t = cur[p - 1];   if (t < m) m = t; }
            if (p >= 128) {
                if (x < 127 && (eg[p - 127] & 2u)) { int t = cur[p - 127]; if (t < m) m = t; }
                if (eg[p - 128] & 4u)              { int t = cur[p - 128]; if (t < m) m = t; }
                if (x > 0 && (eg[p - 129] & 8u))   { int t = cur[p - 129]; if (t < m) m = t; }
            }
            nxt[p] = (unsigned short)m;
            changed |= (m != old);
        }
        if (changed) flags[it] = 1;
        __syncthreads();
        unsigned short* t = cur; cur = nxt; nxt = t;
        if (!flags[it]) break;   // fixed point: all remaining iterations identity
    }

    // ---- relabel: presence bitmap + popcount prefix scan ----
    if (tid < 512) bits[tid] = 0u;
    __syncthreads();
    #pragma unroll
    for (int i = 0; i < 16; i++) {
        int lab = cur[tid + i * 1024];
        atomicOr(&bits[lab >> 5], 1u << (lab & 31));
    }
    __syncthreads();
    if (tid < 512) {
        int lane = tid & 31;
        int pc = __popc(bits[tid]);
        int v = pc;
        #pragma unroll
        for (int o = 1; o < 32; o <<= 1) {
            int t = __shfl_up_sync(0xFFFFFFFFu, v, o);
            if (lane >= o) v += t;
        }
        wpfx[tid] = v - pc;
        if (lane == 31) wsum[tid >> 5] = v;
    }
    __syncthreads();
    if (tid < 16) {
        int orig = wsum[tid];
        int v = orig;
        #pragma unroll
        for (int o = 1; o < 16; o <<= 1) {
            int t = __shfl_up_sync(0x0000FFFFu, v, o);
            if (tid >= o) v += t;
        }
        wsum[tid] = v - orig;
    }
    __syncthreads();
    #pragma unroll
    for (int i = 0; i < 16; i++) {
        int p = tid + i * 1024;
        int lab = cur[p];
        int w = lab >> 5;
        unsigned mask = (2u << (lab & 31)) - 1u;
        int rank = wpfx[w] + wsum[w >> 5] + __popc(bits[w] & mask) - 1;
        g_seg[img * NPIX + p] = (unsigned char)(rank < 255 ? rank : 255);
    }
}

// ============== K4: per-segment sum / sumsq / count =================
// Thread = one float4 channel group of a pixel; 16 lanes cover a pixel,
// warp = 2 pixels -> 512B fully coalesced per warp-iter. Tiles of 8
// prefetched loads (MLP=8). Register run-length accumulation; global
// atomics (RED, no return) only on segment change.
__global__ void __launch_bounds__(256) k_agg(const float4* __restrict__ feat) {
    int img = blockIdx.y;
    int lane = threadIdx.x & 31;
    int warp = threadIdx.x >> 5;
    int g = lane & 15;          // float4 group 0..15
    int q = lane >> 4;          // pixel parity within warp
    int wix = (blockIdx.x << 3) + warp;   // 0..127, 128 pixels each
    int p0 = (wix << 7) + q;              // stride-2 traversal
    const unsigned char* __restrict__ segp = g_seg + img * NPIX;
    const float4* __restrict__ fp = feat + (size_t)img * (NPIX * 16) + g;

    float4 asum = make_float4(0.f,0.f,0.f,0.f);
    float4 asq  = make_float4(0.f,0.f,0.f,0.f);
    float runlen = 0.f;
    int cur = __ldg(&segp[p0]);

    #pragma unroll 1
    for (int tb = 0; tb < 8; tb++) {
        float4 f[8];
        int s[8];
        #pragma unroll
        for (int j = 0; j < 8; j++) {
            int p = p0 + ((tb * 8 + j) << 1);
            s[j] = __ldg(&segp[p]);
            f[j] = __ldg(&fp[(size_t)p * 16]);
        }
        #pragma unroll
        for (int j = 0; j < 8; j++) {
            if (s[j] != cur) {
                int base = (img * M + cur) * C + (g << 2);
                atomicAdd(&g_sum[base+0], asum.x);
                atomicAdd(&g_sum[base+1], asum.y);
                atomicAdd(&g_sum[base+2], asum.z);
                atomicAdd(&g_sum[base+3], asum.w);
                atomicAdd(&g_sq[base+0], asq.x);
                atomicAdd(&g_sq[base+1], asq.y);
                atomicAdd(&g_sq[base+2], asq.z);
                atomicAdd(&g_sq[base+3], asq.w);
                if (g == 0) atomicAdd(&g_cnt[img * M + cur], runlen);
                cur = s[j];
                asum = make_float4(0.f,0.f,0.f,0.f);
                asq  = make_float4(0.f,0.f,0.f,0.f);
                runlen = 0.f;
            }
            asum.x += f[j].x; asq.x = fmaf(f[j].x, f[j].x, asq.x);
            asum.y += f[j].y; asq.y = fmaf(f[j].y, f[j].y, asq.y);
            asum.z += f[j].z; asq.z = fmaf(f[j].z, f[j].z, asq.z);
            asum.w += f[j].w; asq.w = fmaf(f[j].w, f[j].w, asq.w);
            runlen += 1.f;
        }
    }
    {
        int base = (img * M + cur) * C + (g << 2);
        atomicAdd(&g_sum[base+0], asum.x);
        atomicAdd(&g_sum[base+1], asum.y);
        atomicAdd(&g_sum[base+2], asum.z);
        atomicAdd(&g_sum[base+3], asum.w);
        atomicAdd(&g_sq[base+0], asq.x);
        atomicAdd(&g_sq[base+1], asq.y);
        atomicAdd(&g_sq[base+2], asq.z);
        atomicAdd(&g_sq[base+3], asq.w);
        if (g == 0) atomicAdd(&g_cnt[img * M + cur], runlen);
    }
}

// ================= K5: finalize mean/var ====================
__global__ void k_fin(float* __restrict__ out) {
    int tid = blockIdx.x * blockDim.x + threadIdx.x;
    if (tid >= BT*M*C) return;
    int c = tid & (C - 1);
    int seg = tid >> 6;
    float d = fmaxf(g_cnt[seg], 1.0f);
    float mean = g_sum[tid] / d;
    float var = fmaxf(g_sq[tid] / d - mean * mean, 0.0f);
    size_t ob = (size_t)seg * (2 * C) + c;
    out[ob]     = mean;
    out[ob + C] = var;
}

// ================= launch ====================
extern "C" void kernel_launch(void* const* d_in, const int* in_sizes, int n_in,
                              void* d_out, int out_size) {
    (void)in_sizes; (void)n_in; (void)out_size;
    const float4* feat = (const float4*)d_in[0];
    float* out = (float*)d_out;

    cudaFuncSetAttribute(k_edges, cudaFuncAttributeMaxDynamicSharedMemorySize, K1_SMEM);
    cudaFuncSetAttribute(k_prop,  cudaFuncAttributeMaxDynamicSharedMemorySize, K2_SMEM);

    k_edges<<<dim3(4, 4, BT), 256, K1_SMEM>>>(feat);
    k_prop<<<BT, 1024, K2_SMEM>>>();
    k_agg<<<dim3(16, BT), 256>>>(feat);
    k_fin<<<2048, 256>>>(out);
}